// round 9
// baseline (speedup 1.0000x reference)
#include <cuda_runtime.h>
#include <cuda_bf16.h>
#include <math.h>
#include <stdint.h>

#define B_   64
#define S_   512
#define H_   1024
#define M_   (B_ * S_)      // 32768
#define TWOH 2048

#define BM 128
#define BN 256
#define NSTEP 32            // 16 int8 steps (k128) + 16 bf16 steps (k64)
#define NBLK (H_ / BN)      // 4 n-tiles
#define THREADS 512
#define STAGES 4
#define A_BYTES (BM * 128)              // 16384
#define B_BYTES (BN * 128)              // 32768
#define STAGE_BYTES (A_BYTES + B_BYTES) // 49152
#define DSMEM (STAGES * STAGE_BYTES)    // 196608

#define SW128(o) ((o) ^ (((o) >> 3) & 0x70))
#define CSCALE 2.38418579101562e-07f    // 2^-22

// ---------------- scratch ----------------
__device__ float g_d[B_ * H_];
__device__ float g_part[NBLK * M_];
__device__ float g_atmp[M_];
__device__ __nv_bfloat16 g_ah[(size_t)M_ * H_];
__device__ signed char   g_qa [(size_t)M_ * H_];  // s8(16*A)
__device__ signed char   g_qal[(size_t)M_ * H_];  // s8(4096*Al)
__device__ __nv_bfloat16 g_bh[(size_t)H_ * H_];
__device__ signed char   g_qb [(size_t)H_ * H_];  // s8(1024*B)
__device__ signed char   g_qbl[(size_t)H_ * H_];  // s8(2^18*Bl)

// ---------------- helpers ----------------
__device__ __forceinline__ uint32_t smem_u32(const void* p) {
    uint32_t a;
    asm("{ .reg .u64 t; cvta.to.shared.u64 t, %1; cvt.u32.u64 %0, t; }"
        : "=r"(a) : "l"(p));
    return a;
}
__device__ __forceinline__ void cp_async16(uint32_t s, const void* g) {
    asm volatile("cp.async.cg.shared.global [%0], [%1], 16;" :: "r"(s), "l"(g) : "memory");
}
__device__ __forceinline__ void ldsm4(uint32_t* r, uint32_t a) {
    asm volatile("ldmatrix.sync.aligned.m8n8.x4.shared.b16 {%0,%1,%2,%3}, [%4];"
                 : "=r"(r[0]), "=r"(r[1]), "=r"(r[2]), "=r"(r[3]) : "r"(a));
}
__device__ __forceinline__ void mma_bf16(float* c, const uint32_t* a,
                                         uint32_t b0, uint32_t b1) {
    asm volatile(
        "mma.sync.aligned.m16n8k16.row.col.f32.bf16.bf16.f32 "
        "{%0,%1,%2,%3}, {%4,%5,%6,%7}, {%8,%9}, {%0,%1,%2,%3};"
        : "+f"(c[0]), "+f"(c[1]), "+f"(c[2]), "+f"(c[3])
        : "r"(a[0]), "r"(a[1]), "r"(a[2]), "r"(a[3]), "r"(b0), "r"(b1));
}
__device__ __forceinline__ void mma_s8(int* c, const uint32_t* a,
                                       uint32_t b0, uint32_t b1) {
    asm volatile(
        "mma.sync.aligned.m16n8k32.row.col.s32.s8.s8.s32 "
        "{%0,%1,%2,%3}, {%4,%5,%6,%7}, {%8,%9}, {%0,%1,%2,%3};"
        : "+r"(c[0]), "+r"(c[1]), "+r"(c[2]), "+r"(c[3])
        : "r"(a[0]), "r"(a[1]), "r"(a[2]), "r"(a[3]), "r"(b0), "r"(b1));
}
__device__ __forceinline__ signed char toq(float x) {
    float y = fminf(fmaxf(rintf(x), -127.f), 127.f);
    return (signed char)(int)y;
}

// ------------------------------------------------------------------
// enc conversion: bf16 hi + s8(16*A) + s8(4096*Al), 16 floats/thread
// ------------------------------------------------------------------
__global__ void k_conv_enc(const float* __restrict__ x)
{
    size_t base = ((size_t)blockIdx.x * 256 + threadIdx.x) * 16;
    float f[16];
#pragma unroll
    for (int q = 0; q < 4; q++) *(float4*)(f + 4 * q) = *(const float4*)(x + base + 4 * q);
    __nv_bfloat16 h[16];
    signed char qa[16], ql[16];
#pragma unroll
    for (int j = 0; j < 16; j++) {
        h[j] = __float2bfloat16_rn(f[j]);
        qa[j] = toq(16.0f * f[j]);
        ql[j] = toq(4096.0f * (f[j] - __bfloat162float(h[j])));
    }
    *(uint4*)(g_ah + base)     = ((uint4*)h)[0];
    *(uint4*)(g_ah + base + 8) = ((uint4*)h)[1];
    *(uint4*)(g_qa + base)  = *(uint4*)qa;
    *(uint4*)(g_qal + base) = *(uint4*)ql;
}

// ------------------------------------------------------------------
// W conversion (cols H..2H, [n][k]): bf16 hi + s8(1024*B) + s8(2^18*Bl)
// ------------------------------------------------------------------
__global__ void k_conv_w(const float* __restrict__ W)
{
    size_t base = ((size_t)blockIdx.x * 256 + threadIdx.x) * 16;
    size_t n = base >> 10;
    size_t k = base & 1023;
    const float* src = W + n * TWOH + H_ + k;
    float f[16];
#pragma unroll
    for (int q = 0; q < 4; q++) *(float4*)(f + 4 * q) = *(const float4*)(src + 4 * q);
    __nv_bfloat16 h[16];
    signed char qb[16], ql[16];
#pragma unroll
    for (int j = 0; j < 16; j++) {
        h[j] = __float2bfloat16_rn(f[j]);
        qb[j] = toq(1024.0f * f[j]);
        ql[j] = toq(262144.0f * (f[j] - __bfloat162float(h[j])));
    }
    *(uint4*)(g_bh + base)     = ((uint4*)h)[0];
    *(uint4*)(g_bh + base + 8) = ((uint4*)h)[1];
    *(uint4*)(g_qb + base)  = *(uint4*)qb;
    *(uint4*)(g_qbl + base) = *(uint4*)ql;
}

// ------------------------------------------------------------------
// d[b,h] = dec[b,:] . W[h, 0:H] — 8 batch rows per block
// ------------------------------------------------------------------
__global__ void k_dproj(const float* __restrict__ dec, const float* __restrict__ W)
{
    int b0 = blockIdx.y * 8;
    int h = blockIdx.x * 256 + threadIdx.x;
    __shared__ float sd[8][H_];
    for (int i = threadIdx.x; i < 8 * H_; i += 256)
        sd[i >> 10][i & 1023] = dec[b0 * H_ + i];
    __syncthreads();

    const float4* w4 = (const float4*)(W + (size_t)h * TWOH);
    float acc[8];
#pragma unroll
    for (int b = 0; b < 8; b++) acc[b] = 0.f;
#pragma unroll 4
    for (int k4 = 0; k4 < H_ / 4; k4++) {
        float4 w = w4[k4];
#pragma unroll
        for (int b = 0; b < 8; b++)
            acc[b] += w.x * sd[b][4 * k4] + w.y * sd[b][4 * k4 + 1]
                    + w.z * sd[b][4 * k4 + 2] + w.w * sd[b][4 * k4 + 3];
    }
#pragma unroll
    for (int b = 0; b < 8; b++) g_d[(b0 + b) * H_ + h] = acc[b];
}

// ------------------------------------------------------------------
// GEMM: steps 0-7 s8 (16A)x(2^18 Bl), 8-15 s8 (4096 Al)x(1024 B)
// [both at combined scale 2^22], acc_f = acc_i * 2^-22,
// steps 16-31 bf16 Ah x Bh. Fused tanh(.+d).v epilogue.
// ------------------------------------------------------------------
__global__ void __launch_bounds__(THREADS, 1)
k_gemm(const float* __restrict__ v)
{
    extern __shared__ char smem[];
    const uint32_t sbase = smem_u32(smem);

    __shared__ float dsh[BN], vsh[BN];
    __shared__ float red[4][BM];

    const int tid = threadIdx.x;
    const int lane = tid & 31;
    const int wid = tid >> 5;
    const int warp_m = wid & 3;
    const int warp_n = wid >> 2;
    const int m0 = blockIdx.y * BM;
    const int n0 = blockIdx.x * BN;
    const int b  = m0 >> 9;

    if (tid < BN) {
        dsh[tid] = g_d[b * H_ + n0 + tid];
        vsh[tid] = v[n0 + tid];
    }

    // ldsm addressing
    const uint32_t x = (lane & 7) << 4;
    const uint32_t z = (((lane >> 4) & 1) << 4) ^ x;
    uint32_t w[4];
#pragma unroll
    for (int kc = 0; kc < 4; kc++) w[kc] = (uint32_t)(kc * 32) ^ z;

    const int rlo = ((lane >> 3) & 1) * 8 + (lane & 7);
    uint32_t aBase[2], bBase[4];
#pragma unroll
    for (int i = 0; i < 2; i++)
        aBase[i] = sbase + (warp_m * 32 + i * 16 + rlo) * 128;
#pragma unroll
    for (int jp = 0; jp < 4; jp++)
        bBase[jp] = sbase + A_BYTES + (warp_n * 64 + jp * 16 + rlo) * 128;

    // cp.async addressing
    uint32_t dstA[2], dstB[4];
    uint32_t offA8[2], offA16[2], offB8[4], offB16[4];
#pragma unroll
    for (int i = 0; i < 2; i++) {
        int idx = tid + i * THREADS;
        int row = idx >> 3, c16 = idx & 7;
        dstA[i] = sbase + SW128(row * 128 + c16 * 16);
        offA8[i]  = (uint32_t)(m0 + row) * H_     + c16 * 16;
        offA16[i] = (uint32_t)(m0 + row) * H_ * 2 + c16 * 16;
    }
#pragma unroll
    for (int i = 0; i < 4; i++) {
        int idx = tid + i * THREADS;
        int row = idx >> 3, c16 = idx & 7;
        dstB[i] = sbase + A_BYTES + SW128(row * 128 + c16 * 16);
        offB8[i]  = (uint32_t)(n0 + row) * H_     + c16 * 16;
        offB16[i] = (uint32_t)(n0 + row) * H_ * 2 + c16 * 16;
    }

    auto prefetch = [&](int step, int stage) {
        const uint32_t so = stage * STAGE_BYTES;
        const char* As;
        const char* Bs;
        uint32_t kk;
        bool i8;
        if (step < 8)       { As = (const char*)g_qa;  Bs = (const char*)g_qbl; kk = step * 128;        i8 = true; }
        else if (step < 16) { As = (const char*)g_qal; Bs = (const char*)g_qb;  kk = (step - 8) * 128;  i8 = true; }
        else                { As = (const char*)g_ah;  Bs = (const char*)g_bh;  kk = (step - 16) * 128; i8 = false; }
#pragma unroll
        for (int i = 0; i < 2; i++)
            cp_async16(dstA[i] + so, As + (i8 ? offA8[i] : offA16[i]) + kk);
#pragma unroll
        for (int i = 0; i < 4; i++)
            cp_async16(dstB[i] + so, Bs + (i8 ? offB8[i] : offB16[i]) + kk);
        asm volatile("cp.async.commit_group;" ::: "memory");
    };

    prefetch(0, 0);
    prefetch(1, 1);
    prefetch(2, 2);

    // ---- phase 1: int8 corrections (steps 0..15), int32 accumulators ----
    int iacc[2][8][4];
#pragma unroll
    for (int i = 0; i < 2; i++)
#pragma unroll
        for (int j = 0; j < 8; j++)
#pragma unroll
            for (int q = 0; q < 4; q++) iacc[i][j][q] = 0;

    for (int it = 0; it < 4; it++) {
#pragma unroll
        for (int st = 0; st < STAGES; st++) {
            const int step = it * STAGES + st;
            asm volatile("cp.async.wait_group 2;" ::: "memory");
            __syncthreads();
            prefetch(step + 3, (st + 3) & 3);
            const uint32_t so = st * STAGE_BYTES;
#pragma unroll
            for (int kc = 0; kc < 4; kc++) {
                uint32_t a[2][4];
#pragma unroll
                for (int i = 0; i < 2; i++)
                    ldsm4(a[i], aBase[i] + so + w[kc]);
#pragma unroll
                for (int jp = 0; jp < 4; jp++) {
                    uint32_t br[4];
                    ldsm4(br, bBase[jp] + so + w[kc]);
#pragma unroll
                    for (int i = 0; i < 2; i++) {
                        mma_s8(iacc[i][2 * jp],     a[i], br[0], br[2]);
                        mma_s8(iacc[i][2 * jp + 1], a[i], br[1], br[3]);
                    }
                }
            }
        }
    }

    // rescale corrections into float accumulators
    float acc[2][8][4];
#pragma unroll
    for (int i = 0; i < 2; i++)
#pragma unroll
        for (int j = 0; j < 8; j++)
#pragma unroll
            for (int q = 0; q < 4; q++) acc[i][j][q] = (float)iacc[i][j][q] * CSCALE;

    // ---- phase 2: bf16 main term (steps 16..31) ----
    for (int it = 4; it < 8; it++) {
#pragma unroll
        for (int st = 0; st < STAGES; st++) {
            const int step = it * STAGES + st;
            asm volatile("cp.async.wait_group 2;" ::: "memory");
            __syncthreads();
            if (step + 3 < NSTEP) prefetch(step + 3, (st + 3) & 3);
            const uint32_t so = st * STAGE_BYTES;
#pragma unroll
            for (int kc = 0; kc < 4; kc++) {
                uint32_t a[2][4];
#pragma unroll
                for (int i = 0; i < 2; i++)
                    ldsm4(a[i], aBase[i] + so + w[kc]);
#pragma unroll
                for (int jp = 0; jp < 4; jp++) {
                    uint32_t br[4];
                    ldsm4(br, bBase[jp] + so + w[kc]);
#pragma unroll
                    for (int i = 0; i < 2; i++) {
                        mma_bf16(acc[i][2 * jp],     a[i], br[0], br[2]);
                        mma_bf16(acc[i][2 * jp + 1], a[i], br[1], br[3]);
                    }
                }
            }
        }
    }
    asm volatile("cp.async.wait_group 0;" ::: "memory");
    __syncthreads();

    // epilogue: tanh(C + d) . v over this tile's 256 n-columns
#pragma unroll
    for (int i = 0; i < 2; i++) {
        float r0 = 0.f, r1 = 0.f;
#pragma unroll
        for (int j = 0; j < 8; j++) {
            int n = warp_n * 64 + j * 8 + (lane & 3) * 2;
            r0 += tanhf(acc[i][j][0] + dsh[n]) * vsh[n]
                + tanhf(acc[i][j][1] + dsh[n + 1]) * vsh[n + 1];
            r1 += tanhf(acc[i][j][2] + dsh[n]) * vsh[n]
                + tanhf(acc[i][j][3] + dsh[n + 1]) * vsh[n + 1];
        }
        r0 += __shfl_xor_sync(0xffffffffu, r0, 1);
        r0 += __shfl_xor_sync(0xffffffffu, r0, 2);
        r1 += __shfl_xor_sync(0xffffffffu, r1, 1);
        r1 += __shfl_xor_sync(0xffffffffu, r1, 2);
        if ((lane & 3) == 0) {
            int mloc = warp_m * 32 + i * 16 + (lane >> 2);
            red[warp_n][mloc]     = r0;
            red[warp_n][mloc + 8] = r1;
        }
    }
    __syncthreads();
    if (tid < BM) {
        float s = red[0][tid] + red[1][tid] + red[2][tid] + red[3][tid];
        g_part[(size_t)blockIdx.x * M_ + m0 + tid] = s;
    }
}

// ------------------------------------------------------------------
// softmax over batch dim (axis 0) per s, * mask
// ------------------------------------------------------------------
__global__ void k_softmax_b(const float* __restrict__ mask)
{
    int s = blockIdx.x;
    int b = threadIdx.x;
    float val = 0.f;
#pragma unroll
    for (int p = 0; p < NBLK; p++) val += g_part[(size_t)p * M_ + b * S_ + s];

    __shared__ float wmax[2], wsum[2];
    float mx = val;
#pragma unroll
    for (int o = 16; o; o >>= 1) mx = fmaxf(mx, __shfl_xor_sync(0xffffffffu, mx, o));
    if ((b & 31) == 0) wmax[b >> 5] = mx;
    __syncthreads();
    mx = fmaxf(wmax[0], wmax[1]);

    float e = expf(val - mx);
    float sum = e;
#pragma unroll
    for (int o = 16; o; o >>= 1) sum += __shfl_xor_sync(0xffffffffu, sum, o);
    if ((b & 31) == 0) wsum[b >> 5] = sum;
    __syncthreads();
    sum = wsum[0] + wsum[1];

    g_atmp[b * S_ + s] = (e / sum) * mask[s * B_ + b];
}

// ------------------------------------------------------------------
// per-b renormalize over s
// ------------------------------------------------------------------
__global__ void k_norm(float* __restrict__ out)
{
    int b = blockIdx.x;
    int t = threadIdx.x;
    float val = g_atmp[b * S_ + t];
    float s = val;
#pragma unroll
    for (int o = 16; o; o >>= 1) s += __shfl_xor_sync(0xffffffffu, s, o);
    __shared__ float ws[16];
    if ((t & 31) == 0) ws[t >> 5] = s;
    __syncthreads();
    if (t < 32) {
        float x = (t < 16) ? ws[t] : 0.f;
#pragma unroll
        for (int o = 16; o; o >>= 1) x += __shfl_xor_sync(0xffffffffu, x, o);
        if (t == 0) ws[0] = x;
    }
    __syncthreads();
    out[b * S_ + t] = val / (ws[0] + 1e-10f);
}

// ------------------------------------------------------------------
// context[b,h] = sum_s a[b,s] * enc[b,s,h]  — float4 per thread
// ------------------------------------------------------------------
__global__ void k_context(const float* __restrict__ enc,
                          const float* __restrict__ a,
                          float* __restrict__ ctx)
{
    int b = blockIdx.y;
    int h0 = blockIdx.x * 512 + threadIdx.x * 4;
    __shared__ float ash[S_];
    for (int i = threadIdx.x; i < S_; i += 128) ash[i] = a[b * S_ + i];
    __syncthreads();

    const float* e = enc + (size_t)b * S_ * H_ + h0;
    float ax = 0.f, ay = 0.f, az = 0.f, aw = 0.f;
#pragma unroll 8
    for (int s = 0; s < S_; s++) {
        float4 f = *(const float4*)(e + (size_t)s * H_);
        float wgt = ash[s];
        ax += wgt * f.x; ay += wgt * f.y; az += wgt * f.z; aw += wgt * f.w;
    }
    *(float4*)(ctx + b * H_ + h0) = make_float4(ax, ay, az, aw);
}

// ------------------------------------------------------------------
extern "C" void kernel_launch(void* const* d_in, const int* in_sizes, int n_in,
                              void* d_out, int out_size)
{
    const float* enc  = (const float*)d_in[0];  // [B,S,H]
    const float* dec  = (const float*)d_in[1];  // [B,H]
    const float* mask = (const float*)d_in[2];  // [S,B]
    const float* W    = (const float*)d_in[3];  // [H,2H]
    const float* v    = (const float*)d_in[4];  // [H]
    float* out = (float*)d_out;                 // a [B,1,S] then context [B,1,H]

    cudaFuncSetAttribute(k_gemm, cudaFuncAttributeMaxDynamicSharedMemorySize, DSMEM);

    k_conv_enc<<<(size_t)M_ * H_ / 4096, 256>>>(enc);
    k_conv_w<<<(size_t)H_ * H_ / 4096, 256>>>(W);
    k_dproj<<<dim3(H_ / 256, B_ / 8), 256>>>(dec, W);
    k_gemm<<<dim3(NBLK, M_ / BM), THREADS, DSMEM>>>(v);
    k_softmax_b<<<S_, B_>>>(mask);
    k_norm<<<B_, S_>>>(out);
    k_context<<<dim3(2, B_), 128>>>(enc, out, out + M_);
}

// round 14
// speedup vs baseline: 1.8529x; 1.8529x over previous
#include <cuda_runtime.h>
#include <cuda_bf16.h>
#include <math.h>
#include <stdint.h>

#define B_   64
#define S_   512
#define H_   1024
#define M_   (B_ * S_)      // 32768
#define TWOH 2048

#define BM 128
#define BN 128
#define NSTEP 48            // 3 segments * 16 k-steps (k64 each)
#define NBLK (H_ / BN)      // 8 n-tiles
#define THREADS 256
#define STAGES 3
#define A_BYTES (BM * 128)              // 16384
#define B_BYTES (BN * 128)              // 16384
#define STAGE_BYTES (A_BYTES + B_BYTES) // 32768
#define DSMEM (STAGES * STAGE_BYTES)    // 98304

#define SW128(o) ((o) ^ (((o) >> 3) & 0x70))

// ---------------- scratch ----------------
__device__ float g_d[B_ * H_];
__device__ float g_part[NBLK * M_];
__device__ float g_atmp[M_];
__device__ __nv_bfloat16 g_ah[(size_t)M_ * H_];
__device__ __nv_bfloat16 g_al[(size_t)M_ * H_];
__device__ __nv_bfloat16 g_bh[(size_t)H_ * H_];
__device__ __nv_bfloat16 g_bl[(size_t)H_ * H_];

// ---------------- helpers ----------------
__device__ __forceinline__ uint32_t smem_u32(const void* p) {
    uint32_t a;
    asm("{ .reg .u64 t; cvta.to.shared.u64 t, %1; cvt.u32.u64 %0, t; }"
        : "=r"(a) : "l"(p));
    return a;
}
__device__ __forceinline__ void cp_async16(uint32_t s, const void* g) {
    asm volatile("cp.async.cg.shared.global [%0], [%1], 16;" :: "r"(s), "l"(g) : "memory");
}
__device__ __forceinline__ void ldsm4(uint32_t* r, uint32_t a) {
    asm volatile("ldmatrix.sync.aligned.m8n8.x4.shared.b16 {%0,%1,%2,%3}, [%4];"
                 : "=r"(r[0]), "=r"(r[1]), "=r"(r[2]), "=r"(r[3]) : "r"(a));
}
__device__ __forceinline__ void mma_bf16(float* c, const uint32_t* a,
                                         uint32_t b0, uint32_t b1) {
    asm volatile(
        "mma.sync.aligned.m16n8k16.row.col.f32.bf16.bf16.f32 "
        "{%0,%1,%2,%3}, {%4,%5,%6,%7}, {%8,%9}, {%0,%1,%2,%3};"
        : "+f"(c[0]), "+f"(c[1]), "+f"(c[2]), "+f"(c[3])
        : "r"(a[0]), "r"(a[1]), "r"(a[2]), "r"(a[3]), "r"(b0), "r"(b1));
}
__device__ __forceinline__ void split16(const float* f, __nv_bfloat16* h, __nv_bfloat16* l) {
#pragma unroll
    for (int j = 0; j < 16; j++) {
        h[j] = __float2bfloat16_rn(f[j]);
        l[j] = __float2bfloat16_rn(f[j] - __bfloat162float(h[j]));
    }
}

// ------------------------------------------------------------------
// fp32 -> bf16 hi/lo split, enc (16 floats per thread)
// ------------------------------------------------------------------
__global__ void k_conv_enc(const float* __restrict__ x)
{
    size_t base = ((size_t)blockIdx.x * 256 + threadIdx.x) * 16;
    float f[16];
#pragma unroll
    for (int q = 0; q < 4; q++) *(float4*)(f + 4 * q) = *(const float4*)(x + base + 4 * q);
    __nv_bfloat16 h[16], l[16];
    split16(f, h, l);
    *(uint4*)(g_ah + base)     = ((uint4*)h)[0];
    *(uint4*)(g_ah + base + 8) = ((uint4*)h)[1];
    *(uint4*)(g_al + base)     = ((uint4*)l)[0];
    *(uint4*)(g_al + base + 8) = ((uint4*)l)[1];
}

// ------------------------------------------------------------------
// fp32 -> bf16 hi/lo split, W second half (cols H..2H), as [n][k]
// ------------------------------------------------------------------
__global__ void k_conv_w(const float* __restrict__ W)
{
    size_t base = ((size_t)blockIdx.x * 256 + threadIdx.x) * 16;
    size_t n = base >> 10;
    size_t k = base & 1023;
    const float* src = W + n * TWOH + H_ + k;
    float f[16];
#pragma unroll
    for (int q = 0; q < 4; q++) *(float4*)(f + 4 * q) = *(const float4*)(src + 4 * q);
    __nv_bfloat16 h[16], l[16];
    split16(f, h, l);
    *(uint4*)(g_bh + base)     = ((uint4*)h)[0];
    *(uint4*)(g_bh + base + 8) = ((uint4*)h)[1];
    *(uint4*)(g_bl + base)     = ((uint4*)l)[0];
    *(uint4*)(g_bl + base + 8) = ((uint4*)l)[1];
}

// ------------------------------------------------------------------
// d[b,h] = dec[b,:] . W[h, 0:H] — 8 batch rows per block
// ------------------------------------------------------------------
__global__ void k_dproj(const float* __restrict__ dec, const float* __restrict__ W)
{
    int b0 = blockIdx.y * 8;
    int h = blockIdx.x * 256 + threadIdx.x;
    __shared__ float sd[8][H_];
    for (int i = threadIdx.x; i < 8 * H_; i += 256)
        sd[i >> 10][i & 1023] = dec[b0 * H_ + i];
    __syncthreads();

    const float4* w4 = (const float4*)(W + (size_t)h * TWOH);
    float acc[8];
#pragma unroll
    for (int b = 0; b < 8; b++) acc[b] = 0.f;
#pragma unroll 4
    for (int k4 = 0; k4 < H_ / 4; k4++) {
        float4 w = w4[k4];
#pragma unroll
        for (int b = 0; b < 8; b++)
            acc[b] += w.x * sd[b][4 * k4] + w.y * sd[b][4 * k4 + 1]
                    + w.z * sd[b][4 * k4 + 2] + w.w * sd[b][4 * k4 + 3];
    }
#pragma unroll
    for (int b = 0; b < 8; b++) g_d[(b0 + b) * H_ + h] = acc[b];
}

// ------------------------------------------------------------------
// HMMA GEMM: 256 threads, CTA 128x128, warp tile 32x64 (4m x 2n),
// 3-stage cp.async pipeline with prefetch distance 2 (race-free:
// consume s%3, in-flight (s+1)%3, prefetch (s+2)%3), 2 CTAs/SM.
// Fused tanh(.+d).v epilogue into g_part[nblk][m].
// ------------------------------------------------------------------
__global__ void __launch_bounds__(THREADS, 2)
k_gemm(const float* __restrict__ v)
{
    extern __shared__ char smem[];
    const uint32_t sbase = smem_u32(smem);

    __shared__ float dsh[BN], vsh[BN];
    __shared__ float red[2][BM];

    const int tid = threadIdx.x;
    const int lane = tid & 31;
    const int wid = tid >> 5;
    const int warp_m = wid & 3;       // 4 warps along M (32 rows each)
    const int warp_n = wid >> 2;      // 2 warps along N (64 cols each)
    const int m0 = blockIdx.y * BM;
    const int n0 = blockIdx.x * BN;
    const int b  = m0 >> 9;

    if (tid < BN) {
        dsh[tid] = g_d[b * H_ + n0 + tid];
        vsh[tid] = v[n0 + tid];
    }

    // ---- ldsm addressing (precomputed) ----
    const uint32_t x = (lane & 7) << 4;
    const uint32_t z = (((lane >> 4) & 1) << 4) ^ x;
    uint32_t w[4];
#pragma unroll
    for (int kc = 0; kc < 4; kc++) w[kc] = (uint32_t)(kc * 32) ^ z;

    const int rlo = ((lane >> 3) & 1) * 8 + (lane & 7);
    uint32_t aBase[2], bBase[4];
#pragma unroll
    for (int i = 0; i < 2; i++)
        aBase[i] = sbase + (warp_m * 32 + i * 16 + rlo) * 128;
#pragma unroll
    for (int jp = 0; jp < 4; jp++)
        bBase[jp] = sbase + A_BYTES + (warp_n * 64 + jp * 16 + rlo) * 128;

    // ---- cp.async addressing (precomputed) ----
    uint32_t dstA[4], dstB[4], srcA[4], srcB[4];
#pragma unroll
    for (int i = 0; i < 4; i++) {
        int idx = tid + i * THREADS;              // 0..1023
        int row = idx >> 3, c16 = idx & 7;
        dstA[i] = sbase + SW128(row * 128 + c16 * 16);
        srcA[i] = (uint32_t)(m0 + row) * H_ + c16 * 8;
        dstB[i] = sbase + A_BYTES + SW128(row * 128 + c16 * 16);
        srcB[i] = (uint32_t)(n0 + row) * H_ + c16 * 8;
    }

    float acc[2][8][4];
#pragma unroll
    for (int i = 0; i < 2; i++)
#pragma unroll
        for (int j = 0; j < 8; j++)
#pragma unroll
            for (int q = 0; q < 4; q++) acc[i][j][q] = 0.f;

    auto prefetch = [&](int step, int stage) {
        const int seg = step >> 4;
        const uint32_t kkl = (uint32_t)(step & 15) * 64;
        const __nv_bfloat16* Asrc = (seg == 1) ? g_al : g_ah;
        const __nv_bfloat16* Bsrc = (seg == 2) ? g_bl : g_bh;
        const uint32_t so = stage * STAGE_BYTES;
#pragma unroll
        for (int i = 0; i < 4; i++)
            cp_async16(dstA[i] + so, Asrc + srcA[i] + kkl);
#pragma unroll
        for (int i = 0; i < 4; i++)
            cp_async16(dstB[i] + so, Bsrc + srcB[i] + kkl);
        asm volatile("cp.async.commit_group;" ::: "memory");
    };

    prefetch(0, 0);
    prefetch(1, 1);

    for (int it = 0; it < NSTEP / STAGES; it++) {
#pragma unroll
        for (int st = 0; st < STAGES; st++) {
            const int step = it * STAGES + st;
            // groups committed: step, step+1. Wait for group 'step'.
            asm volatile("cp.async.wait_group 1;" ::: "memory");
            __syncthreads();
            // prefetch into stage (st+2)%3: disjoint from consumed (st)
            // and in-flight (st+1)%3; last read at step-1, sealed by the
            // __syncthreads above.
            if (step + 2 < NSTEP) prefetch(step + 2, (st + 2) % STAGES);

            const uint32_t so = st * STAGE_BYTES;
#pragma unroll
            for (int kc = 0; kc < 4; kc++) {
                uint32_t a[2][4];
#pragma unroll
                for (int i = 0; i < 2; i++)
                    ldsm4(a[i], aBase[i] + so + w[kc]);
#pragma unroll
                for (int jp = 0; jp < 4; jp++) {
                    uint32_t br[4];
                    ldsm4(br, bBase[jp] + so + w[kc]);
#pragma unroll
                    for (int i = 0; i < 2; i++) {
                        mma_bf16(acc[i][2 * jp],     a[i], br[0], br[2]);
                        mma_bf16(acc[i][2 * jp + 1], a[i], br[1], br[3]);
                    }
                }
            }
        }
    }
    asm volatile("cp.async.wait_group 0;" ::: "memory");
    __syncthreads();

    // epilogue: tanh(C + d) . v over this tile's 128 n-columns
#pragma unroll
    for (int i = 0; i < 2; i++) {
        float r0 = 0.f, r1 = 0.f;
#pragma unroll
        for (int j = 0; j < 8; j++) {
            int n = warp_n * 64 + j * 8 + (lane & 3) * 2;
            r0 += tanhf(acc[i][j][0] + dsh[n]) * vsh[n]
                + tanhf(acc[i][j][1] + dsh[n + 1]) * vsh[n + 1];
            r1 += tanhf(acc[i][j][2] + dsh[n]) * vsh[n]
                + tanhf(acc[i][j][3] + dsh[n + 1]) * vsh[n + 1];
        }
        r0 += __shfl_xor_sync(0xffffffffu, r0, 1);
        r0 += __shfl_xor_sync(0xffffffffu, r0, 2);
        r1 += __shfl_xor_sync(0xffffffffu, r1, 1);
        r1 += __shfl_xor_sync(0xffffffffu, r1, 2);
        if ((lane & 3) == 0) {
            int mloc = warp_m * 32 + i * 16 + (lane >> 2);
            red[warp_n][mloc]     = r0;
            red[warp_n][mloc + 8] = r1;
        }
    }
    __syncthreads();
    if (tid < BM) {
        float s = red[0][tid] + red[1][tid];
        g_part[(size_t)blockIdx.x * M_ + m0 + tid] = s;
    }
}

// ------------------------------------------------------------------
// softmax over batch dim (axis 0) per s, * mask
// ------------------------------------------------------------------
__global__ void k_softmax_b(const float* __restrict__ mask)
{
    int s = blockIdx.x;
    int b = threadIdx.x;
    float val = 0.f;
#pragma unroll
    for (int p = 0; p < NBLK; p++) val += g_part[(size_t)p * M_ + b * S_ + s];

    __shared__ float wmax[2], wsum[2];
    float mx = val;
#pragma unroll
    for (int o = 16; o; o >>= 1) mx = fmaxf(mx, __shfl_xor_sync(0xffffffffu, mx, o));
    if ((b & 31) == 0) wmax[b >> 5] = mx;
    __syncthreads();
    mx = fmaxf(wmax[0], wmax[1]);

    float e = expf(val - mx);
    float sum = e;
#pragma unroll
    for (int o = 16; o; o >>= 1) sum += __shfl_xor_sync(0xffffffffu, sum, o);
    if ((b & 31) == 0) wsum[b >> 5] = sum;
    __syncthreads();
    sum = wsum[0] + wsum[1];

    g_atmp[b * S_ + s] = (e / sum) * mask[s * B_ + b];
}

// ------------------------------------------------------------------
// per-b renormalize over s
// ------------------------------------------------------------------
__global__ void k_norm(float* __restrict__ out)
{
    int b = blockIdx.x;
    int t = threadIdx.x;
    float val = g_atmp[b * S_ + t];
    float s = val;
#pragma unroll
    for (int o = 16; o; o >>= 1) s += __shfl_xor_sync(0xffffffffu, s, o);
    __shared__ float ws[16];
    if ((t & 31) == 0) ws[t >> 5] = s;
    __syncthreads();
    if (t < 32) {
        float x = (t < 16) ? ws[t] : 0.f;
#pragma unroll
        for (int o = 16; o; o >>= 1) x += __shfl_xor_sync(0xffffffffu, x, o);
        if (t == 0) ws[0] = x;
    }
    __syncthreads();
    out[b * S_ + t] = val / (ws[0] + 1e-10f);
}

// ------------------------------------------------------------------
// context[b,h] = sum_s a[b,s] * enc[b,s,h]  — float4 per thread
// ------------------------------------------------------------------
__global__ void k_context(const float* __restrict__ enc,
                          const float* __restrict__ a,
                          float* __restrict__ ctx)
{
    int b = blockIdx.y;
    int h0 = blockIdx.x * 512 + threadIdx.x * 4;
    __shared__ float ash[S_];
    for (int i = threadIdx.x; i < S_; i += 128) ash[i] = a[b * S_ + i];
    __syncthreads();

    const float* e = enc + (size_t)b * S_ * H_ + h0;
    float ax = 0.f, ay = 0.f, az = 0.f, aw = 0.f;
#pragma unroll 8
    for (int s = 0; s < S_; s++) {
        float4 f = *(const float4*)(e + (size_t)s * H_);
        float wgt = ash[s];
        ax += wgt * f.x; ay += wgt * f.y; az += wgt * f.z; aw += wgt * f.w;
    }
    *(float4*)(ctx + b * H_ + h0) = make_float4(ax, ay, az, aw);
}

// ------------------------------------------------------------------
extern "C" void kernel_launch(void* const* d_in, const int* in_sizes, int n_in,
                              void* d_out, int out_size)
{
    const float* enc  = (const float*)d_in[0];  // [B,S,H]
    const float* dec  = (const float*)d_in[1];  // [B,H]
    const float* mask = (const float*)d_in[2];  // [S,B]
    const float* W    = (const float*)d_in[3];  // [H,2H]
    const float* v    = (const float*)d_in[4];  // [H]
    float* out = (float*)d_out;                 // a [B,1,S] then context [B,1,H]

    cudaFuncSetAttribute(k_gemm, cudaFuncAttributeMaxDynamicSharedMemorySize, DSMEM);

    k_conv_enc<<<(size_t)M_ * H_ / 4096, 256>>>(enc);
    k_conv_w<<<(size_t)H_ * H_ / 4096, 256>>>(W);
    k_dproj<<<dim3(H_ / 256, B_ / 8), 256>>>(dec, W);
    k_gemm<<<dim3(NBLK, M_ / BM), THREADS, DSMEM>>>(v);
    k_softmax_b<<<S_, B_>>>(mask);
    k_norm<<<B_, S_>>>(out);
    k_context<<<dim3(2, B_), 128>>>(enc, out, out + M_);
}

// round 15
// speedup vs baseline: 1.8558x; 1.0016x over previous
#include <cuda_runtime.h>
#include <cuda_bf16.h>
#include <math.h>
#include <stdint.h>

#define B_   64
#define S_   512
#define H_   1024
#define M_   (B_ * S_)      // 32768
#define TWOH 2048

#define BM 128
#define BN 128
#define NSTEP 48            // 3 segments * 16 k-steps (k64 each)
#define NBLK (H_ / BN)      // 8 n-tiles
#define THREADS 256
#define STAGES 3
#define A_BYTES (BM * 128)              // 16384
#define B_BYTES (BN * 128)              // 16384
#define STAGE_BYTES (A_BYTES + B_BYTES) // 32768
#define DSMEM (STAGES * STAGE_BYTES)    // 98304

#define SW128(o) ((o) ^ (((o) >> 3) & 0x70))

// ---------------- scratch ----------------
__device__ float g_d[B_ * H_];
__device__ float g_part[NBLK * M_];
__device__ float g_atmp[M_];
__device__ __nv_bfloat16 g_ah[(size_t)M_ * H_];
__device__ __nv_bfloat16 g_al[(size_t)M_ * H_];
__device__ __nv_bfloat16 g_bh[(size_t)H_ * H_];
__device__ __nv_bfloat16 g_bl[(size_t)H_ * H_];

// ---------------- helpers ----------------
__device__ __forceinline__ uint32_t smem_u32(const void* p) {
    uint32_t a;
    asm("{ .reg .u64 t; cvta.to.shared.u64 t, %1; cvt.u32.u64 %0, t; }"
        : "=r"(a) : "l"(p));
    return a;
}
__device__ __forceinline__ void cp_async16(uint32_t s, const void* g) {
    asm volatile("cp.async.cg.shared.global [%0], [%1], 16;" :: "r"(s), "l"(g) : "memory");
}
__device__ __forceinline__ void ldsm4(uint32_t* r, uint32_t a) {
    asm volatile("ldmatrix.sync.aligned.m8n8.x4.shared.b16 {%0,%1,%2,%3}, [%4];"
                 : "=r"(r[0]), "=r"(r[1]), "=r"(r[2]), "=r"(r[3]) : "r"(a));
}
__device__ __forceinline__ void mma_bf16(float* c, const uint32_t* a,
                                         uint32_t b0, uint32_t b1) {
    asm volatile(
        "mma.sync.aligned.m16n8k16.row.col.f32.bf16.bf16.f32 "
        "{%0,%1,%2,%3}, {%4,%5,%6,%7}, {%8,%9}, {%0,%1,%2,%3};"
        : "+f"(c[0]), "+f"(c[1]), "+f"(c[2]), "+f"(c[3])
        : "r"(a[0]), "r"(a[1]), "r"(a[2]), "r"(a[3]), "r"(b0), "r"(b1));
}
__device__ __forceinline__ void split16(const float* f, __nv_bfloat16* h, __nv_bfloat16* l) {
#pragma unroll
    for (int j = 0; j < 16; j++) {
        h[j] = __float2bfloat16_rn(f[j]);
        l[j] = __float2bfloat16_rn(f[j] - __bfloat162float(h[j]));
    }
}

// ------------------------------------------------------------------
// fp32 -> bf16 hi/lo split, enc (16 floats per thread)
// ------------------------------------------------------------------
__global__ void k_conv_enc(const float* __restrict__ x)
{
    size_t base = ((size_t)blockIdx.x * 256 + threadIdx.x) * 16;
    float f[16];
#pragma unroll
    for (int q = 0; q < 4; q++) *(float4*)(f + 4 * q) = *(const float4*)(x + base + 4 * q);
    __nv_bfloat16 h[16], l[16];
    split16(f, h, l);
    *(uint4*)(g_ah + base)     = ((uint4*)h)[0];
    *(uint4*)(g_ah + base + 8) = ((uint4*)h)[1];
    *(uint4*)(g_al + base)     = ((uint4*)l)[0];
    *(uint4*)(g_al + base + 8) = ((uint4*)l)[1];
}

// ------------------------------------------------------------------
// fp32 -> bf16 hi/lo split, W second half (cols H..2H), as [n][k]
// ------------------------------------------------------------------
__global__ void k_conv_w(const float* __restrict__ W)
{
    size_t base = ((size_t)blockIdx.x * 256 + threadIdx.x) * 16;
    size_t n = base >> 10;
    size_t k = base & 1023;
    const float* src = W + n * TWOH + H_ + k;
    float f[16];
#pragma unroll
    for (int q = 0; q < 4; q++) *(float4*)(f + 4 * q) = *(const float4*)(src + 4 * q);
    __nv_bfloat16 h[16], l[16];
    split16(f, h, l);
    *(uint4*)(g_bh + base)     = ((uint4*)h)[0];
    *(uint4*)(g_bh + base + 8) = ((uint4*)h)[1];
    *(uint4*)(g_bl + base)     = ((uint4*)l)[0];
    *(uint4*)(g_bl + base + 8) = ((uint4*)l)[1];
}

// ------------------------------------------------------------------
// d[b,h] = dec[b,:] . W[h, 0:H] — 8 batch rows per block
// ------------------------------------------------------------------
__global__ void k_dproj(const float* __restrict__ dec, const float* __restrict__ W)
{
    int b0 = blockIdx.y * 8;
    int h = blockIdx.x * 256 + threadIdx.x;
    __shared__ float sd[8][H_];
    for (int i = threadIdx.x; i < 8 * H_; i += 256)
        sd[i >> 10][i & 1023] = dec[b0 * H_ + i];
    __syncthreads();

    const float4* w4 = (const float4*)(W + (size_t)h * TWOH);
    float acc[8];
#pragma unroll
    for (int b = 0; b < 8; b++) acc[b] = 0.f;
#pragma unroll 4
    for (int k4 = 0; k4 < H_ / 4; k4++) {
        float4 w = w4[k4];
#pragma unroll
        for (int b = 0; b < 8; b++)
            acc[b] += w.x * sd[b][4 * k4] + w.y * sd[b][4 * k4 + 1]
                    + w.z * sd[b][4 * k4 + 2] + w.w * sd[b][4 * k4 + 3];
    }
#pragma unroll
    for (int b = 0; b < 8; b++) g_d[(b0 + b) * H_ + h] = acc[b];
}

// ------------------------------------------------------------------
// HMMA GEMM: 256 threads, CTA 128x128, warp tile 32x64 (4m x 2n),
// 3-stage cp.async pipeline with prefetch distance 2 (race-free:
// consume s%3, in-flight (s+1)%3, prefetch (s+2)%3), 2 CTAs/SM.
// Fused tanh(.+d).v epilogue into g_part[nblk][m].
// ------------------------------------------------------------------
__global__ void __launch_bounds__(THREADS, 2)
k_gemm(const float* __restrict__ v)
{
    extern __shared__ char smem[];
    const uint32_t sbase = smem_u32(smem);

    __shared__ float dsh[BN], vsh[BN];
    __shared__ float red[2][BM];

    const int tid = threadIdx.x;
    const int lane = tid & 31;
    const int wid = tid >> 5;
    const int warp_m = wid & 3;       // 4 warps along M (32 rows each)
    const int warp_n = wid >> 2;      // 2 warps along N (64 cols each)
    const int m0 = blockIdx.y * BM;
    const int n0 = blockIdx.x * BN;
    const int b  = m0 >> 9;

    if (tid < BN) {
        dsh[tid] = g_d[b * H_ + n0 + tid];
        vsh[tid] = v[n0 + tid];
    }

    // ---- ldsm addressing (precomputed) ----
    const uint32_t x = (lane & 7) << 4;
    const uint32_t z = (((lane >> 4) & 1) << 4) ^ x;
    uint32_t w[4];
#pragma unroll
    for (int kc = 0; kc < 4; kc++) w[kc] = (uint32_t)(kc * 32) ^ z;

    const int rlo = ((lane >> 3) & 1) * 8 + (lane & 7);
    uint32_t aBase[2], bBase[4];
#pragma unroll
    for (int i = 0; i < 2; i++)
        aBase[i] = sbase + (warp_m * 32 + i * 16 + rlo) * 128;
#pragma unroll
    for (int jp = 0; jp < 4; jp++)
        bBase[jp] = sbase + A_BYTES + (warp_n * 64 + jp * 16 + rlo) * 128;

    // ---- cp.async addressing (precomputed) ----
    uint32_t dstA[4], dstB[4], srcA[4], srcB[4];
#pragma unroll
    for (int i = 0; i < 4; i++) {
        int idx = tid + i * THREADS;              // 0..1023
        int row = idx >> 3, c16 = idx & 7;
        dstA[i] = sbase + SW128(row * 128 + c16 * 16);
        srcA[i] = (uint32_t)(m0 + row) * H_ + c16 * 8;
        dstB[i] = sbase + A_BYTES + SW128(row * 128 + c16 * 16);
        srcB[i] = (uint32_t)(n0 + row) * H_ + c16 * 8;
    }

    float acc[2][8][4];
#pragma unroll
    for (int i = 0; i < 2; i++)
#pragma unroll
        for (int j = 0; j < 8; j++)
#pragma unroll
            for (int q = 0; q < 4; q++) acc[i][j][q] = 0.f;

    auto prefetch = [&](int step, int stage) {
        const int seg = step >> 4;
        const uint32_t kkl = (uint32_t)(step & 15) * 64;
        const __nv_bfloat16* Asrc = (seg == 1) ? g_al : g_ah;
        const __nv_bfloat16* Bsrc = (seg == 2) ? g_bl : g_bh;
        const uint32_t so = stage * STAGE_BYTES;
#pragma unroll
        for (int i = 0; i < 4; i++)
            cp_async16(dstA[i] + so, Asrc + srcA[i] + kkl);
#pragma unroll
        for (int i = 0; i < 4; i++)
            cp_async16(dstB[i] + so, Bsrc + srcB[i] + kkl);
        asm volatile("cp.async.commit_group;" ::: "memory");
    };

    prefetch(0, 0);
    prefetch(1, 1);

    for (int it = 0; it < NSTEP / STAGES; it++) {
#pragma unroll
        for (int st = 0; st < STAGES; st++) {
            const int step = it * STAGES + st;
            // groups committed: step, step+1. Wait for group 'step'.
            asm volatile("cp.async.wait_group 1;" ::: "memory");
            __syncthreads();
            // prefetch into stage (st+2)%3: disjoint from consumed (st)
            // and in-flight (st+1)%3; last read at step-1, sealed by the
            // __syncthreads above.
            if (step + 2 < NSTEP) prefetch(step + 2, (st + 2) % STAGES);

            const uint32_t so = st * STAGE_BYTES;
#pragma unroll
            for (int kc = 0; kc < 4; kc++) {
                uint32_t a[2][4];
#pragma unroll
                for (int i = 0; i < 2; i++)
                    ldsm4(a[i], aBase[i] + so + w[kc]);
#pragma unroll
                for (int jp = 0; jp < 4; jp++) {
                    uint32_t br[4];
                    ldsm4(br, bBase[jp] + so + w[kc]);
#pragma unroll
                    for (int i = 0; i < 2; i++) {
                        mma_bf16(acc[i][2 * jp],     a[i], br[0], br[2]);
                        mma_bf16(acc[i][2 * jp + 1], a[i], br[1], br[3]);
                    }
                }
            }
        }
    }
    asm volatile("cp.async.wait_group 0;" ::: "memory");
    __syncthreads();

    // epilogue: tanh(C + d) . v over this tile's 128 n-columns
#pragma unroll
    for (int i = 0; i < 2; i++) {
        float r0 = 0.f, r1 = 0.f;
#pragma unroll
        for (int j = 0; j < 8; j++) {
            int n = warp_n * 64 + j * 8 + (lane & 3) * 2;
            r0 += tanhf(acc[i][j][0] + dsh[n]) * vsh[n]
                + tanhf(acc[i][j][1] + dsh[n + 1]) * vsh[n + 1];
            r1 += tanhf(acc[i][j][2] + dsh[n]) * vsh[n]
                + tanhf(acc[i][j][3] + dsh[n + 1]) * vsh[n + 1];
        }
        r0 += __shfl_xor_sync(0xffffffffu, r0, 1);
        r0 += __shfl_xor_sync(0xffffffffu, r0, 2);
        r1 += __shfl_xor_sync(0xffffffffu, r1, 1);
        r1 += __shfl_xor_sync(0xffffffffu, r1, 2);
        if ((lane & 3) == 0) {
            int mloc = warp_m * 32 + i * 16 + (lane >> 2);
            red[warp_n][mloc]     = r0;
            red[warp_n][mloc + 8] = r1;
        }
    }
    __syncthreads();
    if (tid < BM) {
        float s = red[0][tid] + red[1][tid];
        g_part[(size_t)blockIdx.x * M_ + m0 + tid] = s;
    }
}

// ------------------------------------------------------------------
// softmax over batch dim (axis 0) per s, * mask
// ------------------------------------------------------------------
__global__ void k_softmax_b(const float* __restrict__ mask)
{
    int s = blockIdx.x;
    int b = threadIdx.x;
    float val = 0.f;
#pragma unroll
    for (int p = 0; p < NBLK; p++) val += g_part[(size_t)p * M_ + b * S_ + s];

    __shared__ float wmax[2], wsum[2];
    float mx = val;
#pragma unroll
    for (int o = 16; o; o >>= 1) mx = fmaxf(mx, __shfl_xor_sync(0xffffffffu, mx, o));
    if ((b & 31) == 0) wmax[b >> 5] = mx;
    __syncthreads();
    mx = fmaxf(wmax[0], wmax[1]);

    float e = expf(val - mx);
    float sum = e;
#pragma unroll
    for (int o = 16; o; o >>= 1) sum += __shfl_xor_sync(0xffffffffu, sum, o);
    if ((b & 31) == 0) wsum[b >> 5] = sum;
    __syncthreads();
    sum = wsum[0] + wsum[1];

    g_atmp[b * S_ + s] = (e / sum) * mask[s * B_ + b];
}

// ------------------------------------------------------------------
// per-b renormalize over s
// ------------------------------------------------------------------
__global__ void k_norm(float* __restrict__ out)
{
    int b = blockIdx.x;
    int t = threadIdx.x;
    float val = g_atmp[b * S_ + t];
    float s = val;
#pragma unroll
    for (int o = 16; o; o >>= 1) s += __shfl_xor_sync(0xffffffffu, s, o);
    __shared__ float ws[16];
    if ((t & 31) == 0) ws[t >> 5] = s;
    __syncthreads();
    if (t < 32) {
        float x = (t < 16) ? ws[t] : 0.f;
#pragma unroll
        for (int o = 16; o; o >>= 1) x += __shfl_xor_sync(0xffffffffu, x, o);
        if (t == 0) ws[0] = x;
    }
    __syncthreads();
    out[b * S_ + t] = val / (ws[0] + 1e-10f);
}

// ------------------------------------------------------------------
// context[b,h] = sum_s a[b,s] * enc[b,s,h]  — float4 per thread
// ------------------------------------------------------------------
__global__ void k_context(const float* __restrict__ enc,
                          const float* __restrict__ a,
                          float* __restrict__ ctx)
{
    int b = blockIdx.y;
    int h0 = blockIdx.x * 512 + threadIdx.x * 4;
    __shared__ float ash[S_];
    for (int i = threadIdx.x; i < S_; i += 128) ash[i] = a[b * S_ + i];
    __syncthreads();

    const float* e = enc + (size_t)b * S_ * H_ + h0;
    float ax = 0.f, ay = 0.f, az = 0.f, aw = 0.f;
#pragma unroll 8
    for (int s = 0; s < S_; s++) {
        float4 f = *(const float4*)(e + (size_t)s * H_);
        float wgt = ash[s];
        ax += wgt * f.x; ay += wgt * f.y; az += wgt * f.z; aw += wgt * f.w;
    }
    *(float4*)(ctx + b * H_ + h0) = make_float4(ax, ay, az, aw);
}

// ------------------------------------------------------------------
extern "C" void kernel_launch(void* const* d_in, const int* in_sizes, int n_in,
                              void* d_out, int out_size)
{
    const float* enc  = (const float*)d_in[0];  // [B,S,H]
    const float* dec  = (const float*)d_in[1];  // [B,H]
    const float* mask = (const float*)d_in[2];  // [S,B]
    const float* W    = (const float*)d_in[3];  // [H,2H]
    const float* v    = (const float*)d_in[4];  // [H]
    float* out = (float*)d_out;                 // a [B,1,S] then context [B,1,H]

    cudaFuncSetAttribute(k_gemm, cudaFuncAttributeMaxDynamicSharedMemorySize, DSMEM);

    k_conv_enc<<<(size_t)M_ * H_ / 4096, 256>>>(enc);
    k_conv_w<<<(size_t)H_ * H_ / 4096, 256>>>(W);
    k_dproj<<<dim3(H_ / 256, B_ / 8), 256>>>(dec, W);
    k_gemm<<<dim3(NBLK, M_ / BM), THREADS, DSMEM>>>(v);
    k_softmax_b<<<S_, B_>>>(mask);
    k_norm<<<B_, S_>>>(out);
    k_context<<<dim3(2, B_), 128>>>(enc, out, out + M_);
}